// round 14
// baseline (speedup 1.0000x reference)
#include <cuda_runtime.h>

// Problem constants
#define BQ    8192
#define NSUB  16
#define KC    1024
#define EDIM  16
#define DEPTHQ 3
#define DIMQ  256
#define EPSC  2e-4f   // Gram-path shortlist margin (error bound ~3e-5, 6x margin)
#define D1EPS 1e-5f   // depth-1 sqrt-collapse window (collapse width ~4e-6)

// Output layout: [loss(1), z_q_out(B*256), onehot(B*16*1024), idx(B*16)]
#define OFF_LOSS   ((size_t)0)
#define OFF_ZQ     ((size_t)1)
#define OFF_ONEHOT ((size_t)(1 + BQ * DIMQ))
#define OFF_IDX    ((size_t)(OFF_ONEHOT + (size_t)BQ * NSUB * KC))

__device__ float g_P[(size_t)NSUB * KC * DIMQ];      // 16.8 MB
__device__ int   g_idx[(size_t)BQ * NSUB * DEPTHQ];
__device__ float g_G[(size_t)NSUB * KC * KC];        // 64 MB: 2*<e_k, e_j>

// ---------------- packed f32x2 helpers ----------------
__device__ __forceinline__ unsigned long long pack2(float a, float b) {
    unsigned long long r;
    asm("mov.b64 %0, {%1,%2};" : "=l"(r) : "f"(a), "f"(b));
    return r;
}
__device__ __forceinline__ void fma2(unsigned long long& d, unsigned long long a, unsigned long long b) {
    asm("fma.rn.f32x2 %0, %1, %2, %0;" : "+l"(d) : "l"(a), "l"(b));
}
__device__ __forceinline__ unsigned long long fma2v(unsigned long long a, unsigned long long b, unsigned long long c) {
    unsigned long long r;
    asm("fma.rn.f32x2 %0, %1, %2, %3;" : "=l"(r) : "l"(a), "l"(b), "l"(c));
    return r;
}
__device__ __forceinline__ unsigned long long add2(unsigned long long a, unsigned long long b) {
    unsigned long long r;
    asm("add.rn.f32x2 %0, %1, %2;" : "=l"(r) : "l"(a), "l"(b));
    return r;
}
__device__ __forceinline__ void unpack2(unsigned long long v, float& lo, float& hi) {
    asm("mov.b64 {%0,%1}, %2;" : "=f"(lo), "=f"(hi) : "l"(v));
}
__device__ __forceinline__ float warp_min_f(float v) {
#pragma unroll
    for (int o = 16; o; o >>= 1) v = fminf(v, __shfl_xor_sync(0xffffffffu, v, o));
    return v;
}
__device__ __forceinline__ unsigned long long warp_min_u64(unsigned long long k) {
#pragma unroll
    for (int o = 16; o; o >>= 1) {
        unsigned long long ok = __shfl_xor_sync(0xffffffffu, k, o);
        k = ok < k ? ok : k;
    }
    return k;
}
// key = (bits(d), j): uint order == float order for d >= 0; min -> lowest j on ties
__device__ __forceinline__ unsigned long long mkkey(float dv, int j) {
    return ((unsigned long long)__float_as_uint(dv) << 32) | (unsigned)j;
}

// ---------------- kernel 0: 2*Gram table (validated in R13) ----------------
__global__ void __launch_bounds__(1024, 1)
compute_G_kernel(const float* __restrict__ emb) {
    const int chunk = blockIdx.x;
    const int n = blockIdx.y;
    const int j = threadIdx.x;

    __shared__ float se[64 * EDIM];
    se[j] = emb[(size_t)n * KC * EDIM + (size_t)chunk * 1024 + j];

    float ej[16];
    const float* ejp = emb + (size_t)n * KC * EDIM + (size_t)j * EDIM;
#pragma unroll
    for (int i = 0; i < 16; i++) ej[i] = ejp[i];
    __syncthreads();

    float* gdst = g_G + ((size_t)n << 20) + ((size_t)chunk * 64 << 10) + j;
#pragma unroll 4
    for (int k = 0; k < 64; k++) {
        float c = 0.0f;
#pragma unroll
        for (int i = 0; i < 16; i++) c = fmaf(se[k * EDIM + i], ej[i], c);
        gdst[(size_t)k << 10] = 2.0f * c;
    }
}

// ---------------- kernel 1: P precompute (+ zero loss slot) ----------------
__global__ void compute_P_kernel(const float* __restrict__ emb,
                                 const float* __restrict__ W,
                                 float* __restrict__ out) {
    if (blockIdx.x == 0 && threadIdx.x == 0) out[OFF_LOSS] = 0.0f;

    const int n  = blockIdx.x >> 6;
    const int k0 = (blockIdx.x & 63) * 16;
    const int j  = threadIdx.x;

    __shared__ float se[16 * EDIM];
    se[j] = emb[((size_t)n * KC + k0) * EDIM + j];

    float w[16];
#pragma unroll
    for (int i = 0; i < 16; i++) w[i] = W[(size_t)(n * 16 + i) * DIMQ + j];
    __syncthreads();

#pragma unroll
    for (int kk = 0; kk < 16; kk++) {
        float acc = 0.0f;
#pragma unroll
        for (int i = 0; i < 16; i++) acc = fmaf(se[kk * EDIM + i], w[i], acc);
        g_P[((size_t)n * KC + (k0 + kk)) * DIMQ + j] = acc;
    }
}

// ---------------- kernel 2: VQ — exact depth-1 scan + SMEM scores + Gram depths 2/3 ----------------
// grid (64 row-tiles of 128 rows, 16 n), 256 thr = 8 warps, 16 rows/warp in 4 batches of 4.
// SMEM: cb4 (dim-major float4) 64KB + esq 4KB + s1 (8 warps x 4 rows x 4KB) 128KB + sbk 512B
#define SMF_ESQ  16384
#define SMF_S1   17408
#define SMF_SBK  (17408 + 32768)
#define VQ_SMEM  ((size_t)((SMF_SBK + 128) * 4))

// exact sequential chain i=0..15 over scalar zrs — bit-matches reference contraction
#define CHAIN16S(acc, zrs, A, B, C, D) do {                                       \
    acc = fmaf((zrs)[0],  (A).x, acc); acc = fmaf((zrs)[1],  (A).y, acc);         \
    acc = fmaf((zrs)[2],  (A).z, acc); acc = fmaf((zrs)[3],  (A).w, acc);         \
    acc = fmaf((zrs)[4],  (B).x, acc); acc = fmaf((zrs)[5],  (B).y, acc);         \
    acc = fmaf((zrs)[6],  (B).z, acc); acc = fmaf((zrs)[7],  (B).w, acc);         \
    acc = fmaf((zrs)[8],  (C).x, acc); acc = fmaf((zrs)[9],  (C).y, acc);         \
    acc = fmaf((zrs)[10], (C).z, acc); acc = fmaf((zrs)[11], (C).w, acc);         \
    acc = fmaf((zrs)[12], (D).x, acc); acc = fmaf((zrs)[13], (D).y, acc);         \
    acc = fmaf((zrs)[14], (D).z, acc); acc = fmaf((zrs)[15], (D).w, acc);         \
} while (0)

// one dup-multiplied packed step: both row-pairs advance dim ii with code value E
#define DUPFMA(E, ii) do {                                                        \
    unsigned long long m_ = pack2((E), (E));                                      \
    fma2(a0, zd[0][ii], m_); fma2(a1, zd[1][ii], m_);                             \
} while (0)

__global__ void __launch_bounds__(256)
vq_kernel(const float* __restrict__ z,
          const float* __restrict__ emb,
          float* __restrict__ out) {
    extern __shared__ float smemf[];
    float4* cb4 = (float4*)smemf;                 // [4][1024] dim-major
    float* s_esq = smemf + SMF_ESQ;
    float* s1 = smemf + SMF_S1;                   // [8 warps][4 rows][1024]
    int* sbk = (int*)(smemf + SMF_SBK);           // final idx per local row (128)

    const int n = blockIdx.y;
    const int tid = threadIdx.x;
    const int wid = tid >> 5, lane = tid & 31;

    // Codebook (dim-major) + esq (sequential fmaf chain — matches ref)
    for (int j = tid; j < KC; j += 256) {
        const float4* e4 = (const float4*)(emb + ((size_t)n * KC + j) * EDIM);
        float4 a = e4[0], b = e4[1], c = e4[2], dq = e4[3];
        cb4[j] = a; cb4[KC + j] = b; cb4[2 * KC + j] = c; cb4[3 * KC + j] = dq;
        float es = 0.0f;
        es = fmaf(a.x, a.x, es);  es = fmaf(a.y, a.y, es);
        es = fmaf(a.z, a.z, es);  es = fmaf(a.w, a.w, es);
        es = fmaf(b.x, b.x, es);  es = fmaf(b.y, b.y, es);
        es = fmaf(b.z, b.z, es);  es = fmaf(b.w, b.w, es);
        es = fmaf(c.x, c.x, es);  es = fmaf(c.y, c.y, es);
        es = fmaf(c.z, c.z, es);  es = fmaf(c.w, c.w, es);
        es = fmaf(dq.x, dq.x, es); es = fmaf(dq.y, dq.y, es);
        es = fmaf(dq.z, dq.z, es); es = fmaf(dq.w, dq.w, es);
        s_esq[j] = es;
    }
    __syncthreads();

    const float* twoGn = g_G + ((size_t)n << 20);
    float* s1w = s1 + (size_t)wid * 4096;
    const unsigned long long NEG2 = 0xC0000000C0000000ull;

    for (int batch = 0; batch < 4; ++batch) {
        const int rbase = blockIdx.x * 128 + wid * 16 + batch * 4;   // rows rbase..+3

        // Onehot zero-fill for these 4 rows (overlaps with scan latency)
        for (int rr = 0; rr < 4; rr++) {
            float* dst = out + OFF_ONEHOT + ((size_t)(rbase + rr) * NSUB + n) * KC;
#pragma unroll
            for (int q = 0; q < 32; q++) dst[q * 32 + lane] = 0.0f;
        }

        // Load 4 rows as 2 f32x2 pairs (rows in lanes); zsq sequential chain
        unsigned long long zd[2][16];
        float zsq[4];
#pragma unroll
        for (int p = 0; p < 2; p++) {
            const float* za = z + (size_t)(rbase + 2 * p) * DIMQ + n * EDIM;
            const float* zb = za + DIMQ;
            float sa = 0.0f, sb = 0.0f;
#pragma unroll
            for (int i = 0; i < 16; i++) {
                float a = za[i], b = zb[i];
                zd[p][i] = pack2(a, b);
                sa = fmaf(a, a, sa);
                sb = fmaf(b, b, sb);
            }
            zsq[2 * p] = sa;
            zsq[2 * p + 1] = sb;
        }

        int bkprev[4] = {0, 0, 0, 0};

        for (int d = 0; d < DEPTHQ; d++) {
            float smin[4] = {3.4e38f, 3.4e38f, 3.4e38f, 3.4e38f};

            if (d == 0) {
                // Exact packed scan: lane handles code j = t*32+lane for all 4 rows.
                // Per lane, per row: sequential fmaf chain (bit-matches reference),
                // s = fmaf(-2,c,zsq)+esq. Scores stored to SMEM (exact fp32).
                const unsigned long long zq20 = pack2(zsq[0], zsq[1]);
                const unsigned long long zq21 = pack2(zsq[2], zsq[3]);
#pragma unroll 2
                for (int t = 0; t < 32; t++) {
                    const int j = t * 32 + lane;
                    float4 A = cb4[j], Bv = cb4[KC + j];
                    float4 Cv = cb4[2 * KC + j], Dv = cb4[3 * KC + j];
                    unsigned long long a0 = 0ull, a1 = 0ull;
                    DUPFMA(A.x, 0);  DUPFMA(A.y, 1);  DUPFMA(A.z, 2);  DUPFMA(A.w, 3);
                    DUPFMA(Bv.x, 4); DUPFMA(Bv.y, 5); DUPFMA(Bv.z, 6); DUPFMA(Bv.w, 7);
                    DUPFMA(Cv.x, 8); DUPFMA(Cv.y, 9); DUPFMA(Cv.z, 10); DUPFMA(Cv.w, 11);
                    DUPFMA(Dv.x, 12); DUPFMA(Dv.y, 13); DUPFMA(Dv.z, 14); DUPFMA(Dv.w, 15);
                    const float es = s_esq[j];
                    const unsigned long long es2 = pack2(es, es);
                    unsigned long long s20 = add2(fma2v(a0, NEG2, zq20), es2);
                    unsigned long long s21 = add2(fma2v(a1, NEG2, zq21), es2);
                    float s0, s1v, s2v, s3v;
                    unpack2(s20, s0, s1v);
                    unpack2(s21, s2v, s3v);
                    s1w[j] = s0; s1w[KC + j] = s1v;
                    s1w[2 * KC + j] = s2v; s1w[3 * KC + j] = s3v;
                    smin[0] = fminf(smin[0], s0); smin[1] = fminf(smin[1], s1v);
                    smin[2] = fminf(smin[2], s2v); smin[3] = fminf(smin[3], s3v);
                }
            } else {
                // Gram update (approx, argmin-equivalent up to j-independent shift):
                // s += 2<e_{bkprev}, e_j>. Lane-aligned SMEM (j = t*32+lane): each
                // lane touches only its own written elements -> no syncs needed.
#pragma unroll
                for (int r = 0; r < 4; r++) {
                    const float* grow = twoGn + ((size_t)bkprev[r] << 10);
                    float* s1r = s1w + r * KC;
                    float sm = 3.4e38f;
#pragma unroll 4
                    for (int t = 0; t < 32; t++) {
                        const int j = t * 32 + lane;
                        float sv = s1r[j] + grow[j];
                        s1r[j] = sv;                 // kept for d==2 and candidate pass
                        sm = fminf(sm, sv);
                    }
                    smin[r] = sm;
                }
            }

            // Per-row selection (exact reference semantics)
#pragma unroll 1
            for (int r = 0; r < 4; r++) {
                const float sm = warp_min_f(smin[r]);
                unsigned long long key = 0xFFFFFFFFFFFFFFFFull;
                const float* s1r = s1w + r * KC;

                if (d == 0) {
                    // Stored scores are EXACT. d = sqrt(max(s,0)) is monotone, so
                    // min d = sqrt(max(min s,0)); ties in d (sqrt collapse) resolved
                    // to lowest j via key-min over the tiny candidate set.
                    const float dmin = sqrtf(fmaxf(sm, 0.0f));
                    const float win = sm + D1EPS;
#pragma unroll 1
                    for (int t = 0; t < 32; t++) {
                        const int j = t * 32 + lane;
                        const float s = s1r[j];
                        if (s <= win) {
                            const float dv = sqrtf(fmaxf(s, 0.0f));
                            if (dv <= dmin) {
                                unsigned long long k2 = mkkey(dv, j);
                                key = k2 < key ? k2 : key;
                            }
                        }
                    }
                } else {
                    // Approx scores -> shortlist -> EXACT rescore with the bit-exact
                    // reference chain on the current residual (validated in R13).
                    const float thr = sm + EPSC;
                    float zrs[16];
                    const int p = r >> 1;
#pragma unroll
                    for (int i = 0; i < 16; i++) {
                        float lo, hi;
                        unpack2(zd[p][i], lo, hi);
                        zrs[i] = (r & 1) ? hi : lo;
                    }
                    const float zq = zsq[r];
#pragma unroll 1
                    for (int t = 0; t < 32; t++) {
                        const int j = t * 32 + lane;
                        if (s1r[j] <= thr) {
                            float4 A = cb4[j], Bv = cb4[KC + j];
                            float4 Cv = cb4[2 * KC + j], Dv = cb4[3 * KC + j];
                            float c = 0.0f;
                            CHAIN16S(c, zrs, A, Bv, Cv, Dv);
                            const float s = fmaf(-2.0f, c, zq) + s_esq[j];
                            const float dv = sqrtf(fmaxf(s, 0.0f));
                            unsigned long long k2 = mkkey(dv, j);
                            key = k2 < key ? k2 : key;
                        }
                    }
                }

                key = warp_min_u64(key);
                const int bk = (int)(unsigned)key;
                const int row = rbase + r;

                if (lane == 0) g_idx[((size_t)row * NSUB + n) * DEPTHQ + d] = bk;

                if (d < DEPTHQ - 1) {
                    // Residual update row r (one fp32 sub per component) + zsq chain
                    float4 A = cb4[bk], Bv = cb4[KC + bk];
                    float4 Cv = cb4[2 * KC + bk], Dv = cb4[3 * KC + bk];
                    float e[16] = {A.x, A.y, A.z, A.w, Bv.x, Bv.y, Bv.z, Bv.w,
                                   Cv.x, Cv.y, Cv.z, Cv.w, Dv.x, Dv.y, Dv.z, Dv.w};
                    const int p = r >> 1;
                    float s2 = 0.0f;
#pragma unroll
                    for (int i = 0; i < 16; i++) {
                        float lo, hi;
                        unpack2(zd[p][i], lo, hi);
                        if (r & 1) hi = hi - e[i]; else lo = lo - e[i];
                        const float v = (r & 1) ? hi : lo;
                        s2 = fmaf(v, v, s2);
                        zd[p][i] = pack2(lo, hi);
                    }
                    zsq[r] = s2;
                    bkprev[r] = bk;
                } else if (lane == 0) {
                    out[OFF_IDX + (size_t)row * NSUB + n] = (float)bk;
                    sbk[wid * 16 + batch * 4 + r] = bk;
                }
            }
        }
    }

    // All zero-fills precede this barrier; ones after (proven R7 pattern).
    __syncthreads();
    if (tid < 128) {
        const int row = blockIdx.x * 128 + tid;
        out[OFF_ONEHOT + ((size_t)row * NSUB + n) * KC + sbk[tid]] = 1.0f;
    }
}

// ---------------- kernel 3: z_q gather + z_q_out + loss ----------------
__global__ void gather_out_kernel(const float* __restrict__ z,
                                  const float* __restrict__ bias,
                                  float* __restrict__ out) {
    const int b = blockIdx.x;
    const int j = threadIdx.x;
    __shared__ int sidx[48];
    __shared__ float sred[8];

    if (j < 48) sidx[j] = g_idx[(size_t)b * 48 + j];
    __syncthreads();

    float acc = 0.0f;
#pragma unroll
    for (int n = 0; n < NSUB; n++) {
#pragma unroll
        for (int d = 0; d < DEPTHQ; d++) {
            const int k = sidx[n * 3 + d];
            acc += g_P[(((size_t)n << 10) + k) * DIMQ + j];
        }
    }
    const float zq = acc * (1.0f / 3.0f) + bias[j];
    const float zv = z[(size_t)b * DIMQ + j];
    const float diff = zq - zv;
    out[OFF_ZQ + (size_t)b * DIMQ + j] = zv + diff;

    float p = diff * diff;
#pragma unroll
    for (int off = 16; off > 0; off >>= 1) p += __shfl_down_sync(0xffffffffu, p, off);
    if ((j & 31) == 0) sred[j >> 5] = p;
    __syncthreads();
    if (j == 0) {
        float s = 0.0f;
#pragma unroll
        for (int i = 0; i < 8; i++) s += sred[i];
        atomicAdd(out + OFF_LOSS, s * (1.25f / (float)(BQ * DIMQ)));
    }
}

// ---------------- launcher ----------------
extern "C" void kernel_launch(void* const* d_in, const int* in_sizes, int n_in,
                              void* d_out, int out_size) {
    const float* z    = (const float*)d_in[0];
    const float* emb  = (const float*)d_in[1];
    const float* W    = (const float*)d_in[2];
    const float* bias = (const float*)d_in[3];
    float* out = (float*)d_out;

    (void)in_sizes; (void)n_in; (void)out_size;

    compute_G_kernel<<<dim3(16, 16), 1024>>>(emb);

    cudaFuncSetAttribute(vq_kernel, cudaFuncAttributeMaxDynamicSharedMemorySize, (int)VQ_SMEM);
    vq_kernel<<<dim3(64, 16), 256, VQ_SMEM>>>(z, emb, out);

    compute_P_kernel<<<1024, 256>>>(emb, W, out);

    gather_out_kernel<<<BQ, 256>>>(z, bias, out);
}

// round 15
// speedup vs baseline: 1.2562x; 1.2562x over previous
#include <cuda_runtime.h>

// Problem constants
#define BQ    8192
#define NSUB  16
#define KC    1024
#define EDIM  16
#define DEPTHQ 3
#define DIMQ  256
#define EPSC  2e-4f   // Gram shortlist margin (error bound ~3e-5; validated R13/R14)

// Output layout: [loss(1), z_q_out(B*256), onehot(B*16*1024), idx(B*16)]
#define OFF_LOSS   ((size_t)0)
#define OFF_ZQ     ((size_t)1)
#define OFF_ONEHOT ((size_t)(1 + BQ * DIMQ))
#define OFF_IDX    ((size_t)(OFF_ONEHOT + (size_t)BQ * NSUB * KC))

__device__ float g_P[(size_t)NSUB * KC * DIMQ];
__device__ int   g_idx[(size_t)BQ * NSUB * DEPTHQ];
__device__ float g_G[(size_t)NSUB * KC * KC];        // 2*<e_k, e_j>

// ---------------- packed f32x2 / misc helpers ----------------
__device__ __forceinline__ unsigned long long pack2(float a, float b) {
    unsigned long long r;
    asm("mov.b64 %0, {%1,%2};" : "=l"(r) : "f"(a), "f"(b));
    return r;
}
__device__ __forceinline__ void fma2(unsigned long long& d, unsigned long long a, unsigned long long b) {
    asm("fma.rn.f32x2 %0, %1, %2, %0;" : "+l"(d) : "l"(a), "l"(b));
}
__device__ __forceinline__ unsigned long long fma2v(unsigned long long a, unsigned long long b, unsigned long long c) {
    unsigned long long r;
    asm("fma.rn.f32x2 %0, %1, %2, %3;" : "=l"(r) : "l"(a), "l"(b), "l"(c));
    return r;
}
__device__ __forceinline__ unsigned long long add2(unsigned long long a, unsigned long long b) {
    unsigned long long r;
    asm("add.rn.f32x2 %0, %1, %2;" : "=l"(r) : "l"(a), "l"(b));
    return r;
}
__device__ __forceinline__ void unpack2(unsigned long long v, float& lo, float& hi) {
    asm("mov.b64 {%0,%1}, %2;" : "=f"(lo), "=f"(hi) : "l"(v));
}
__device__ __forceinline__ float warp_min_f(float v) {
#pragma unroll
    for (int o = 16; o; o >>= 1) v = fminf(v, __shfl_xor_sync(0xffffffffu, v, o));
    return v;
}
__device__ __forceinline__ unsigned long long warp_min_u64(unsigned long long k) {
#pragma unroll
    for (int o = 16; o; o >>= 1) {
        unsigned long long ok = __shfl_xor_sync(0xffffffffu, k, o);
        k = ok < k ? ok : k;
    }
    return k;
}
// key = (bits(d) << 32) | j : uint order == float order for d >= 0;
// equal d -> lower j -> exactly first-index argmin over d.
__device__ __forceinline__ unsigned long long mkkey(float dv, int j) {
    return ((unsigned long long)__float_as_uint(dv) << 32) | (unsigned)j;
}

// ---------------- kernel 0: 2*Gram table (validated) ----------------
__global__ void __launch_bounds__(1024, 1)
compute_G_kernel(const float* __restrict__ emb) {
    const int chunk = blockIdx.x;
    const int n = blockIdx.y;
    const int j = threadIdx.x;

    __shared__ float se[64 * EDIM];
    se[j] = emb[(size_t)n * KC * EDIM + (size_t)chunk * 1024 + j];

    float ej[16];
    const float* ejp = emb + (size_t)n * KC * EDIM + (size_t)j * EDIM;
#pragma unroll
    for (int i = 0; i < 16; i++) ej[i] = ejp[i];
    __syncthreads();

    float* gdst = g_G + ((size_t)n << 20) + ((size_t)chunk * 64 << 10) + j;
#pragma unroll 4
    for (int k = 0; k < 64; k++) {
        float c = 0.0f;
#pragma unroll
        for (int i = 0; i < 16; i++) c = fmaf(se[k * EDIM + i], ej[i], c);
        gdst[(size_t)k << 10] = 2.0f * c;
    }
}

// ---------------- kernel 1: P precompute (+ zero loss slot) ----------------
__global__ void compute_P_kernel(const float* __restrict__ emb,
                                 const float* __restrict__ W,
                                 float* __restrict__ out) {
    if (blockIdx.x == 0 && threadIdx.x == 0) out[OFF_LOSS] = 0.0f;

    const int n  = blockIdx.x >> 6;
    const int k0 = (blockIdx.x & 63) * 16;
    const int j  = threadIdx.x;

    __shared__ float se[16 * EDIM];
    se[j] = emb[((size_t)n * KC + k0) * EDIM + j];

    float w[16];
#pragma unroll
    for (int i = 0; i < 16; i++) w[i] = W[(size_t)(n * 16 + i) * DIMQ + j];
    __syncthreads();

#pragma unroll
    for (int kk = 0; kk < 16; kk++) {
        float acc = 0.0f;
#pragma unroll
        for (int i = 0; i < 16; i++) acc = fmaf(se[kk * EDIM + i], w[i], acc);
        g_P[((size_t)n * KC + (k0 + kk)) * DIMQ + j] = acc;
    }
}

// ---------------- kernel 2: VQ — exact packed depth-1 + SMEM scores + Gram depths 2/3 ----------------
// grid (256 tiles of 32 rows, 16 n), 256 threads = 8 warps, 4 rows/warp.
// SMEM floats: cb4 [0,16384) 64KB | esq [16384,17408) | s1 [17408,50176) 128KB | sbk ints
#define SMF_ESQ  16384
#define SMF_S1   17408
#define SMF_SBK  50176
#define VQ_SMEM  ((size_t)((SMF_SBK + 32) * 4))

// exact sequential chain i=0..15 over scalar zrs — bit-matches reference contraction
#define CHAIN16S(acc, zrs, A, B, C, D) do {                                   \
    acc = fmaf((zrs)[0],  (A).x, acc); acc = fmaf((zrs)[1],  (A).y, acc);     \
    acc = fmaf((zrs)[2],  (A).z, acc); acc = fmaf((zrs)[3],  (A).w, acc);     \
    acc = fmaf((zrs)[4],  (B).x, acc); acc = fmaf((zrs)[5],  (B).y, acc);     \
    acc = fmaf((zrs)[6],  (B).z, acc); acc = fmaf((zrs)[7],  (B).w, acc);     \
    acc = fmaf((zrs)[8],  (C).x, acc); acc = fmaf((zrs)[9],  (C).y, acc);     \
    acc = fmaf((zrs)[10], (C).z, acc); acc = fmaf((zrs)[11], (C).w, acc);     \
    acc = fmaf((zrs)[12], (D).x, acc); acc = fmaf((zrs)[13], (D).y, acc);     \
    acc = fmaf((zrs)[14], (D).z, acc); acc = fmaf((zrs)[15], (D).w, acc);     \
} while (0)

// dup-packed FMA step for dim ii with scalar code value E (both row-pairs)
#define DUPFMA(E, ii) do {                                                    \
    unsigned long long m_ = pack2((E), (E));                                  \
    fma2(a0, zd0[ii], m_); fma2(a1, zd1[ii], m_);                             \
} while (0)

// Extract scalar residual of one row from packed zd (HI is a LITERAL 0/1)
#define EXTRACT_ZR(zrs, ZD, HI) do {                                          \
    _Pragma("unroll")                                                         \
    for (int i_ = 0; i_ < 16; i_++) {                                         \
        float lo_, hi_;                                                       \
        unpack2((ZD)[i_], lo_, hi_);                                          \
        (zrs)[i_] = (HI) ? hi_ : lo_;                                         \
    }                                                                         \
} while (0)

// Residual update for one row (LITERAL HI, ZSQ an lvalue): zr -= e[bk],
// one fp32 sub per component + sequential zsq chain — matches reference.
#define RESID_UPDATE(ZD, HI, BK, ZSQ) do {                                    \
    float4 A_ = cb4[BK], B_ = cb4[KC + BK];                                   \
    float4 C_ = cb4[2 * KC + BK], D_ = cb4[3 * KC + BK];                      \
    float ev_[16] = {A_.x, A_.y, A_.z, A_.w, B_.x, B_.y, B_.z, B_.w,          \
                     C_.x, C_.y, C_.z, C_.w, D_.x, D_.y, D_.z, D_.w};         \
    float s2_ = 0.0f;                                                         \
    _Pragma("unroll")                                                         \
    for (int i_ = 0; i_ < 16; i_++) {                                         \
        float lo_, hi_;                                                       \
        unpack2((ZD)[i_], lo_, hi_);                                          \
        if (HI) hi_ = hi_ - ev_[i_]; else lo_ = lo_ - ev_[i_];                \
        const float v_ = (HI) ? hi_ : lo_;                                    \
        s2_ = fmaf(v_, v_, s2_);                                              \
        (ZD)[i_] = pack2(lo_, hi_);                                           \
    }                                                                         \
    ZSQ = s2_;                                                                \
} while (0)

// Gram depth step for one row (LITERAL R / ZD / HI; WB literal: writeback for
// next depth). Approx update s += 2G[bk_prev][j] (argmin-equivalent up to a
// j-independent shift); shortlist (EPSC) -> exact rescore with the bit-exact
// reference chain on the CURRENT residual (machinery validated R13/R14).
#define GRAM_ROW(R, ZD, HI, WB) do {                                          \
    const float* grow_ = twoGn + ((size_t)bkrow[R] << 10);                    \
    float* s1r_ = s1w + (R) * KC;                                             \
    float m_ = 3.4e38f;                                                       \
    _Pragma("unroll")                                                         \
    for (int t_ = 0; t_ < 32; t_++) {                                         \
        const int j_ = t_ * 32 + lane;                                        \
        const float v_ = s1r_[j_] + __ldg(grow_ + j_);                        \
        if (WB) s1r_[j_] = v_;                                                \
        m_ = fminf(m_, v_);                                                   \
    }                                                                         \
    const float sm_ = warp_min_f(m_);                                         \
    const float thr_ = sm_ + EPSC;                                            \
    unsigned long long key_ = 0xFFFFFFFFFFFFFFFFull;                          \
    if (m_ <= thr_) {                                                         \
        float zrs_[16];                                                       \
        EXTRACT_ZR(zrs_, ZD, HI);                                             \
        const float zq_ = zsq[R];                                             \
        _Pragma("unroll 1")                                                   \
        for (int t_ = 0; t_ < 32; t_++) {                                     \
            const int j_ = t_ * 32 + lane;                                    \
            const float v_ = (WB) ? s1r_[j_] : (s1r_[j_] + __ldg(grow_ + j_));\
            if (v_ <= thr_) {                                                 \
                float4 A_ = cb4[j_], B_ = cb4[KC + j_];                       \
                float4 C_ = cb4[2 * KC + j_], D_ = cb4[3 * KC + j_];          \
                float c_ = 0.0f;                                              \
                CHAIN16S(c_, zrs_, A_, B_, C_, D_);                           \
                const float s_ = fmaf(-2.0f, c_, zq_) + s_esq[j_];            \
                const float dv_ = sqrtf(fmaxf(s_, 0.0f));                     \
                unsigned long long k2_ = mkkey(dv_, j_);                      \
                key_ = k2_ < key_ ? k2_ : key_;                               \
            }                                                                 \
        }                                                                     \
    }                                                                         \
    key_ = warp_min_u64(key_);                                                \
    bkrow[R] = (int)(unsigned)key_;                                           \
} while (0)

__global__ void __launch_bounds__(256, 1)
vq_kernel(const float* __restrict__ z,
          const float* __restrict__ emb,
          float* __restrict__ out) {
    extern __shared__ float smemf[];
    float4* cb4 = (float4*)smemf;                 // [4][1024] dim-major
    float* s_esq = smemf + SMF_ESQ;
    float* s1 = smemf + SMF_S1;                   // [32 rows][1024] scores
    int* sbk = (int*)(smemf + SMF_SBK);           // final idx per local row

    const int n = blockIdx.y;
    const int rowbase = blockIdx.x * 32;
    const int tid = threadIdx.x;
    const int wid = tid >> 5, lane = tid & 31;

    // Codebook (dim-major) + esq (sequential fmaf chain — matches ref)
    for (int j = tid; j < KC; j += 256) {
        const float4* e4 = (const float4*)(emb + ((size_t)n * KC + j) * EDIM);
        float4 a = e4[0], b = e4[1], c = e4[2], dq = e4[3];
        cb4[j] = a; cb4[KC + j] = b; cb4[2 * KC + j] = c; cb4[3 * KC + j] = dq;
        float es = 0.0f;
        es = fmaf(a.x, a.x, es);  es = fmaf(a.y, a.y, es);
        es = fmaf(a.z, a.z, es);  es = fmaf(a.w, a.w, es);
        es = fmaf(b.x, b.x, es);  es = fmaf(b.y, b.y, es);
        es = fmaf(b.z, b.z, es);  es = fmaf(b.w, b.w, es);
        es = fmaf(c.x, c.x, es);  es = fmaf(c.y, c.y, es);
        es = fmaf(c.z, c.z, es);  es = fmaf(c.w, c.w, es);
        es = fmaf(dq.x, dq.x, es); es = fmaf(dq.y, dq.y, es);
        es = fmaf(dq.z, dq.z, es); es = fmaf(dq.w, dq.w, es);
        s_esq[j] = es;
    }
    __syncthreads();

    // Onehot zero-fill chunk 0 (rows 0..10 of this tile)
    for (int rl = 0; rl < 11; rl++) {
        float* dst = out + OFF_ONEHOT + ((size_t)(rowbase + rl) * NSUB + n) * KC;
        dst[tid] = 0.0f; dst[tid + 256] = 0.0f;
        dst[tid + 512] = 0.0f; dst[tid + 768] = 0.0f;
    }

    // Warp's 4 rows, packed: zd0 = (row0,row1), zd1 = (row2,row3)
    const int r0 = rowbase + wid * 4;
    unsigned long long zd0[16], zd1[16];
    float zsq[4];
    {
        const float* za = z + (size_t)(r0 + 0) * DIMQ + n * EDIM;
        const float* zb = za + DIMQ;
        const float* zc = zb + DIMQ;
        const float* zdp = zc + DIMQ;
        float s0 = 0.0f, s1v = 0.0f, s2v = 0.0f, s3v = 0.0f;
#pragma unroll
        for (int i = 0; i < 16; i++) {
            float a = za[i], b = zb[i], c = zc[i], dd = zdp[i];
            zd0[i] = pack2(a, b);
            zd1[i] = pack2(c, dd);
            s0 = fmaf(a, a, s0); s1v = fmaf(b, b, s1v);
            s2v = fmaf(c, c, s2v); s3v = fmaf(dd, dd, s3v);
        }
        zsq[0] = s0; zsq[1] = s1v; zsq[2] = s2v; zsq[3] = s3v;
    }

    const float* twoGn = g_G + ((size_t)n << 20);
    float* s1w = s1 + (size_t)(wid * 4) * KC;
    const unsigned long long NEG2 = 0xC0000000C0000000ull;
    int bkrow[4];

    // ---------- depth 0: exact packed scan, scores -> SMEM ----------
    {
        float bs0 = 3.4e38f, bd0 = 3.4e38f; int bk0 = 0;
        float bs1 = 3.4e38f, bd1 = 3.4e38f; int bk1 = 0;
        float bs2 = 3.4e38f, bd2 = 3.4e38f; int bk2 = 0;
        float bs3 = 3.4e38f, bd3 = 3.4e38f; int bk3 = 0;
        const unsigned long long zq20 = pack2(zsq[0], zsq[1]);
        const unsigned long long zq21 = pack2(zsq[2], zsq[3]);

#pragma unroll 4
        for (int t = 0; t < 32; t++) {
            const int j = t * 32 + lane;
            float4 A = cb4[j], Bv = cb4[KC + j];
            float4 Cv = cb4[2 * KC + j], Dv = cb4[3 * KC + j];
            unsigned long long a0 = 0ull, a1 = 0ull;
            DUPFMA(A.x, 0);   DUPFMA(A.y, 1);   DUPFMA(A.z, 2);   DUPFMA(A.w, 3);
            DUPFMA(Bv.x, 4);  DUPFMA(Bv.y, 5);  DUPFMA(Bv.z, 6);  DUPFMA(Bv.w, 7);
            DUPFMA(Cv.x, 8);  DUPFMA(Cv.y, 9);  DUPFMA(Cv.z, 10); DUPFMA(Cv.w, 11);
            DUPFMA(Dv.x, 12); DUPFMA(Dv.y, 13); DUPFMA(Dv.z, 14); DUPFMA(Dv.w, 15);
            const float es = s_esq[j];
            const unsigned long long es2 = pack2(es, es);
            unsigned long long s20 = add2(fma2v(a0, NEG2, zq20), es2);
            unsigned long long s21 = add2(fma2v(a1, NEG2, zq21), es2);
            float v0, v1, v2, v3;
            unpack2(s20, v0, v1);
            unpack2(s21, v2, v3);
            s1w[j] = v0; s1w[KC + j] = v1; s1w[2 * KC + j] = v2; s1w[3 * KC + j] = v3;

            const bool c0 = v0 < bs0; bs0 = fminf(bs0, v0);
            const bool c1 = v1 < bs1; bs1 = fminf(bs1, v1);
            const bool c2 = v2 < bs2; bs2 = fminf(bs2, v2);
            const bool c3 = v3 < bs3; bs3 = fminf(bs3, v3);
            // R7-proven rare branch: d = sqrt(max(s,0)) may collapse adjacent s
            // to equal d -> keep lower j. Ascending j per lane over t.
            if (c0 | c1 | c2 | c3) {
                if (c0) { float dv = sqrtf(fmaxf(v0, 0.0f)); if (dv < bd0) { bd0 = dv; bk0 = j; } }
                if (c1) { float dv = sqrtf(fmaxf(v1, 0.0f)); if (dv < bd1) { bd1 = dv; bk1 = j; } }
                if (c2) { float dv = sqrtf(fmaxf(v2, 0.0f)); if (dv < bd2) { bd2 = dv; bk2 = j; } }
                if (c3) { float dv = sqrtf(fmaxf(v3, 0.0f)); if (dv < bd3) { bd3 = dv; bk3 = j; } }
            }
        }
        // Cross-lane: min over (d, j) keys = global first-index argmin over d.
        bkrow[0] = (int)(unsigned)warp_min_u64(mkkey(bd0, bk0));
        bkrow[1] = (int)(unsigned)warp_min_u64(mkkey(bd1, bk1));
        bkrow[2] = (int)(unsigned)warp_min_u64(mkkey(bd2, bk2));
        bkrow[3] = (int)(unsigned)warp_min_u64(mkkey(bd3, bk3));
    }
    if (lane == 0) {
#pragma unroll
        for (int r = 0; r < 4; r++)
            g_idx[((size_t)(r0 + r) * NSUB + n) * DEPTHQ + 0] = bkrow[r];
    }
    RESID_UPDATE(zd0, 0, bkrow[0], zsq[0]);
    RESID_UPDATE(zd0, 1, bkrow[1], zsq[1]);
    RESID_UPDATE(zd1, 0, bkrow[2], zsq[2]);
    RESID_UPDATE(zd1, 1, bkrow[3], zsq[3]);

    // Onehot zero-fill chunk 1 (rows 11..21)
    for (int rl = 11; rl < 22; rl++) {
        float* dst = out + OFF_ONEHOT + ((size_t)(rowbase + rl) * NSUB + n) * KC;
        dst[tid] = 0.0f; dst[tid + 256] = 0.0f;
        dst[tid + 512] = 0.0f; dst[tid + 768] = 0.0f;
    }

    // ---------- depth 1 (Gram + shortlist, writeback for depth 2) ----------
    GRAM_ROW(0, zd0, 0, 1);
    GRAM_ROW(1, zd0, 1, 1);
    GRAM_ROW(2, zd1, 0, 1);
    GRAM_ROW(3, zd1, 1, 1);
    if (lane == 0) {
#pragma unroll
        for (int r = 0; r < 4; r++)
            g_idx[((size_t)(r0 + r) * NSUB + n) * DEPTHQ + 1] = bkrow[r];
    }
    RESID_UPDATE(zd0, 0, bkrow[0], zsq[0]);
    RESID_UPDATE(zd0, 1, bkrow[1], zsq[1]);
    RESID_UPDATE(zd1, 0, bkrow[2], zsq[2]);
    RESID_UPDATE(zd1, 1, bkrow[3], zsq[3]);

    // Onehot zero-fill chunk 2 (rows 22..31)
    for (int rl = 22; rl < 32; rl++) {
        float* dst = out + OFF_ONEHOT + ((size_t)(rowbase + rl) * NSUB + n) * KC;
        dst[tid] = 0.0f; dst[tid + 256] = 0.0f;
        dst[tid + 512] = 0.0f; dst[tid + 768] = 0.0f;
    }

    // ---------- depth 2 (Gram + shortlist, no writeback) ----------
    GRAM_ROW(0, zd0, 0, 0);
    GRAM_ROW(1, zd0, 1, 0);
    GRAM_ROW(2, zd1, 0, 0);
    GRAM_ROW(3, zd1, 1, 0);
    if (lane == 0) {
#pragma unroll
        for (int r = 0; r < 4; r++) {
            g_idx[((size_t)(r0 + r) * NSUB + n) * DEPTHQ + 2] = bkrow[r];
            out[OFF_IDX + (size_t)(r0 + r) * NSUB + n] = (float)bkrow[r];
            sbk[wid * 4 + r] = bkrow[r];
        }
    }

    // Zero-fills all precede this barrier; ones after.
    __syncthreads();
    if (tid < 32) {
        const int row = rowbase + tid;
        out[OFF_ONEHOT + ((size_t)row * NSUB + n) * KC + sbk[tid]] = 1.0f;
    }
}

// ---------------- kernel 3: z_q gather + z_q_out + loss ----------------
__global__ void gather_out_kernel(const float* __restrict__ z,
                                  const float* __restrict__ bias,
                                  float* __restrict__ out) {
    const int b = blockIdx.x;
    const int j = threadIdx.x;
    __shared__ int sidx[48];
    __shared__ float sred[8];

    if (j < 48) sidx[j] = g_idx[(size_t)b * 48 + j];
    __syncthreads();

    float acc = 0.0f;
#pragma unroll
    for (int n = 0; n < NSUB; n++) {
#pragma unroll
        for (int d = 0; d < DEPTHQ; d++) {
            const int k = sidx[n * 3 + d];
            acc += g_P[(((size_t)n << 10) + k) * DIMQ + j];
        }
    }
    const float zq = acc * (1.0f / 3.0f) + bias[j];
    const float zv = z[(size_t)b * DIMQ + j];
    const float diff = zq - zv;
    out[OFF_ZQ + (size_t)b * DIMQ + j] = zv + diff;

    float p = diff * diff;
#pragma unroll
    for (int off = 16; off > 0; off >>= 1) p += __shfl_down_sync(0xffffffffu, p, off);
    if ((j & 31) == 0) sred[j >> 5] = p;
    __syncthreads();
    if (j == 0) {
        float s = 0.0f;
#pragma unroll
        for (int i = 0; i < 8; i++) s += sred[i];
        atomicAdd(out + OFF_LOSS, s * (1.25f / (float)(BQ * DIMQ)));
    }
}

// ---------------- launcher ----------------
extern "C" void kernel_launch(void* const* d_in, const int* in_sizes, int n_in,
                              void* d_out, int out_size) {
    const float* z    = (const float*)d_in[0];
    const float* emb  = (const float*)d_in[1];
    const float* W    = (const float*)d_in[2];
    const float* bias = (const float*)d_in[3];
    float* out = (float*)d_out;

    (void)in_sizes; (void)n_in; (void)out_size;

    compute_G_kernel<<<dim3(16, 16), 1024>>>(emb);

    cudaFuncSetAttribute(vq_kernel, cudaFuncAttributeMaxDynamicSharedMemorySize, (int)VQ_SMEM);
    vq_kernel<<<dim3(256, 16), 256, VQ_SMEM>>>(z, emb, out);

    compute_P_kernel<<<1024, 256>>>(emb, W, out);

    gather_out_kernel<<<BQ, 256>>>(z, bias, out);
}

// round 16
// speedup vs baseline: 3.1229x; 2.4860x over previous
#include <cuda_runtime.h>

// Problem constants
#define BQ    8192
#define NSUB  16
#define KC    1024
#define EDIM  16
#define DEPTHQ 3
#define DIMQ  256

// Output layout: [loss(1), z_q_out(B*256), onehot(B*16*1024), idx(B*16)]
#define OFF_LOSS   ((size_t)0)
#define OFF_ZQ     ((size_t)1)
#define OFF_ONEHOT ((size_t)(1 + BQ * DIMQ))
#define OFF_IDX    ((size_t)(OFF_ONEHOT + (size_t)BQ * NSUB * KC))

__device__ float g_P[(size_t)NSUB * KC * DIMQ];
__device__ int   g_idx[(size_t)BQ * NSUB * DEPTHQ];

// ---------------- packed f32x2 helpers ----------------
__device__ __forceinline__ unsigned long long pack2(float a, float b) {
    unsigned long long r;
    asm("mov.b64 %0, {%1,%2};" : "=l"(r) : "f"(a), "f"(b));
    return r;
}
__device__ __forceinline__ void fma2(unsigned long long& d, unsigned long long a, unsigned long long b) {
    asm("fma.rn.f32x2 %0, %1, %2, %0;" : "+l"(d) : "l"(a), "l"(b));
}
__device__ __forceinline__ unsigned long long fma2v(unsigned long long a, unsigned long long b, unsigned long long c) {
    unsigned long long r;
    asm("fma.rn.f32x2 %0, %1, %2, %3;" : "=l"(r) : "l"(a), "l"(b), "l"(c));
    return r;
}
__device__ __forceinline__ unsigned long long add2(unsigned long long a, unsigned long long b) {
    unsigned long long r;
    asm("add.rn.f32x2 %0, %1, %2;" : "=l"(r) : "l"(a), "l"(b));
    return r;
}
__device__ __forceinline__ void unpack2(unsigned long long v, float& lo, float& hi) {
    asm("mov.b64 {%0,%1}, %2;" : "=f"(lo), "=f"(hi) : "l"(v));
}

// ---------------- kernel 1: P precompute (+ zero loss slot) ----------------
__global__ void compute_P_kernel(const float* __restrict__ emb,
                                 const float* __restrict__ W,
                                 float* __restrict__ out) {
    if (blockIdx.x == 0 && threadIdx.x == 0) out[OFF_LOSS] = 0.0f;

    const int n  = blockIdx.x >> 6;
    const int k0 = (blockIdx.x & 63) * 16;
    const int j  = threadIdx.x;

    __shared__ float se[16 * EDIM];
    se[j] = emb[((size_t)n * KC + k0) * EDIM + j];

    float w[16];
#pragma unroll
    for (int i = 0; i < 16; i++) w[i] = W[(size_t)(n * 16 + i) * DIMQ + j];
    __syncthreads();

#pragma unroll
    for (int kk = 0; kk < 16; kk++) {
        float acc = 0.0f;
#pragma unroll
        for (int i = 0; i < 16; i++) acc = fmaf(se[kk * EDIM + i], w[i], acc);
        g_P[((size_t)n * KC + (k0 + kk)) * DIMQ + j] = acc;
    }
}

// ---------------- kernel 2: VQ search — R7 proven loop + strip-mined zero-fill ----------------
// grid (16 row-tiles of 512 rows, 16 n), 256 threads, 2 rows/thread, 2 blocks/SM.
#define NKP (KC / 2)
#define VQ_SMEM ((size_t)(NKP * EDIM * 8 + NKP * 8))

__global__ void __launch_bounds__(256, 2)
vq_kernel(const float* __restrict__ z,
          const float* __restrict__ emb,
          float* __restrict__ out) {
    extern __shared__ unsigned long long sm[];
    unsigned long long* pc = sm;                                 // pc[kp*16 + i] = (e[2kp][i], e[2kp+1][i])
    unsigned long long* s_esq = sm + (size_t)NKP * EDIM;         // (esq[2kp], esq[2kp+1])

    const float* pcf = (const float*)pc;  // e[k][i] at pcf[((k>>1)*16 + i)*2 + (k&1)]

    const int n = blockIdx.y;
    const int rowbase = blockIdx.x * 512;
    const int tid = threadIdx.x;

    // Build paired codebook + esq (sequential fmaf chain per code — matches ref)
    for (int kp = tid; kp < NKP; kp += 256) {
        const float* e0 = emb + ((size_t)n * KC + 2 * kp) * EDIM;
        const float* e1 = e0 + EDIM;
        float esq0 = 0.0f, esq1 = 0.0f;
        unsigned long long* m = pc + (size_t)kp * EDIM;
#pragma unroll
        for (int i = 0; i < 16; i++) {
            float v0 = __ldg(e0 + i);
            float v1 = __ldg(e1 + i);
            esq0 = fmaf(v0, v0, esq0);
            esq1 = fmaf(v1, v1, esq1);
            m[i] = pack2(v0, v1);
        }
        s_esq[kp] = pack2(esq0, esq1);
    }
    __syncthreads();

    // Two rows per thread: A = rowbase+tid, B = rowbase+256+tid.
    const int bA = rowbase + tid;
    const int bB = rowbase + 256 + tid;
    unsigned long long zdA[16], zdB[16];
    unsigned long long zsqA2, zsqB2;
    {
        const float* zA = z + (size_t)bA * DIMQ + n * EDIM;
        const float* zB = z + (size_t)bB * DIMQ + n * EDIM;
        float sA = 0.0f, sB = 0.0f;
#pragma unroll
        for (int i = 0; i < 16; i++) {
            float a = zA[i], b = zB[i];
            zdA[i] = pack2(a, a);
            zdB[i] = pack2(b, b);
            sA = fmaf(a, a, sA);
            sB = fmaf(b, b, sB);
        }
        zsqA2 = pack2(sA, sA);
        zsqB2 = pack2(sB, sB);
    }

    const unsigned long long NEG2 = 0xC0000000C0000000ull;  // (-2.f, -2.f)

    int bkA_last = 0, bkB_last = 0;
    int zrow = 0;   // strip-mined onehot zero-fill row counter (0..511)

    for (int d = 0; d < DEPTHQ; d++) {
        float bsA = 3.4e38f, bdA = 3.4e38f;
        float bsB = 3.4e38f, bdB = 3.4e38f;
        int bkA = 0, bkB = 0;

        // Two kp (= 4 codes) per iteration: 4 independent 16-deep FMA chains
        // per thread (proven R7 body). Zero-fill stores strip-mined into the
        // loop (every 8th kp2, 6 rows x 4 scalar stores) so DRAM writes drain
        // continuously under the latency-bound scan instead of in serialized
        // per-depth bursts.
#pragma unroll 1
        for (int kp2 = 0; kp2 < NKP / 2; ++kp2) {
            if ((kp2 & 7) == 0) {
#pragma unroll
                for (int u = 0; u < 6; u++) {
                    if (zrow < 512) {
                        float* dst = out + OFF_ONEHOT
                                   + ((size_t)((rowbase + zrow) * NSUB + n)) * KC + tid;
                        dst[0] = 0.0f; dst[256] = 0.0f; dst[512] = 0.0f; dst[768] = 0.0f;
                    }
                    zrow++;
                }
            }

            const ulonglong2* mv0 = (const ulonglong2*)(pc + (size_t)(2 * kp2) * EDIM);
            const ulonglong2* mv1 = mv0 + 8;
            const ulonglong2 es2 = *((const ulonglong2*)(s_esq + 2 * kp2));

            unsigned long long aA0 = 0ull, aB0 = 0ull, aA1 = 0ull, aB1 = 0ull;
            // 4 staged sub-chunks (peak m-regs 16). Per chain, sequential
            // i = 0..15 — bit-matches the scalar fmaf chain.
#pragma unroll
            for (int c = 0; c < 4; c++) {
                ulonglong2 p0 = mv0[2 * c], q0 = mv0[2 * c + 1];
                ulonglong2 p1 = mv1[2 * c], q1 = mv1[2 * c + 1];
                const int i = 4 * c;
                fma2(aA0, zdA[i + 0], p0.x); fma2(aB0, zdB[i + 0], p0.x);
                fma2(aA1, zdA[i + 0], p1.x); fma2(aB1, zdB[i + 0], p1.x);
                fma2(aA0, zdA[i + 1], p0.y); fma2(aB0, zdB[i + 1], p0.y);
                fma2(aA1, zdA[i + 1], p1.y); fma2(aB1, zdB[i + 1], p1.y);
                fma2(aA0, zdA[i + 2], q0.x); fma2(aB0, zdB[i + 2], q0.x);
                fma2(aA1, zdA[i + 2], q1.x); fma2(aB1, zdB[i + 2], q1.x);
                fma2(aA0, zdA[i + 3], q0.y); fma2(aB0, zdB[i + 3], q0.y);
                fma2(aA1, zdA[i + 3], q1.y); fma2(aB1, zdB[i + 3], q1.y);
            }

            // per lane: s = fmaf(-2, c, zsq) + es  (bit-equal to zsq - 2c, then +es)
            unsigned long long sA02 = add2(fma2v(aA0, NEG2, zsqA2), es2.x);
            unsigned long long sB02 = add2(fma2v(aB0, NEG2, zsqB2), es2.x);
            unsigned long long sA12 = add2(fma2v(aA1, NEG2, zsqA2), es2.y);
            unsigned long long sB12 = add2(fma2v(aB1, NEG2, zsqB2), es2.y);

            float sA0l, sA0h, sA1l, sA1h, sB0l, sB0h, sB1l, sB1h;
            unpack2(sA02, sA0l, sA0h);
            unpack2(sB02, sB0l, sB0h);
            unpack2(sA12, sA1l, sA1h);
            unpack2(sB12, sB1l, sB1h);

            // Ascending code order: 4kp2, 4kp2+1, 4kp2+2, 4kp2+3.
            const bool cA0l = sA0l < bsA; bsA = fminf(bsA, sA0l);
            const bool cA0h = sA0h < bsA; bsA = fminf(bsA, sA0h);
            const bool cA1l = sA1l < bsA; bsA = fminf(bsA, sA1l);
            const bool cA1h = sA1h < bsA; bsA = fminf(bsA, sA1h);
            const bool cB0l = sB0l < bsB; bsB = fminf(bsB, sB0l);
            const bool cB0h = sB0h < bsB; bsB = fminf(bsB, sB0h);
            const bool cB1l = sB1l < bsB; bsB = fminf(bsB, sB1l);
            const bool cB1h = sB1h < bsB; bsB = fminf(bsB, sB1h);

            // Rare path: reference compares d = sqrt(max(s,0)); sqrt can collapse
            // adjacent s -> equal d -> argmin keeps the LOWER index. Updates in
            // strict ascending-k order preserve first-index tie-break exactly.
            if (cA0l | cA0h | cA1l | cA1h | cB0l | cB0h | cB1l | cB1h) {
                const int kb = 4 * kp2;
                if (cA0l) { float dv = sqrtf(fmaxf(sA0l, 0.0f)); if (dv < bdA) { bdA = dv; bkA = kb; } }
                if (cA0h) { float dv = sqrtf(fmaxf(sA0h, 0.0f)); if (dv < bdA) { bdA = dv; bkA = kb + 1; } }
                if (cA1l) { float dv = sqrtf(fmaxf(sA1l, 0.0f)); if (dv < bdA) { bdA = dv; bkA = kb + 2; } }
                if (cA1h) { float dv = sqrtf(fmaxf(sA1h, 0.0f)); if (dv < bdA) { bdA = dv; bkA = kb + 3; } }
                if (cB0l) { float dv = sqrtf(fmaxf(sB0l, 0.0f)); if (dv < bdB) { bdB = dv; bkB = kb; } }
                if (cB0h) { float dv = sqrtf(fmaxf(sB0h, 0.0f)); if (dv < bdB) { bdB = dv; bkB = kb + 1; } }
                if (cB1l) { float dv = sqrtf(fmaxf(sB1l, 0.0f)); if (dv < bdB) { bdB = dv; bkB = kb + 2; } }
                if (cB1h) { float dv = sqrtf(fmaxf(sB1h, 0.0f)); if (dv < bdB) { bdB = dv; bkB = kb + 3; } }
            }
        }

        // Residual update (one fp32 sub per component, matching ref), zsq refresh
        {
            const size_t baseA = ((size_t)(bkA >> 1) * EDIM) * 2 + (bkA & 1);
            const size_t baseB = ((size_t)(bkB >> 1) * EDIM) * 2 + (bkB & 1);
            float sA = 0.0f, sB = 0.0f;
#pragma unroll
            for (int i = 0; i < 16; i++) {
                float a, dummy, b;
                unpack2(zdA[i], a, dummy);
                unpack2(zdB[i], b, dummy);
                a = a - pcf[baseA + 2 * i];
                b = b - pcf[baseB + 2 * i];
                sA = fmaf(a, a, sA);
                sB = fmaf(b, b, sB);
                zdA[i] = pack2(a, a);
                zdB[i] = pack2(b, b);
            }
            zsqA2 = pack2(sA, sA);
            zsqB2 = pack2(sB, sB);
        }

        g_idx[((size_t)bA * NSUB + n) * DEPTHQ + d] = bkA;
        g_idx[((size_t)bB * NSUB + n) * DEPTHQ + d] = bkB;
        if (d == DEPTHQ - 1) {
            bkA_last = bkA;
            bkB_last = bkB;
            out[OFF_IDX + (size_t)bA * NSUB + n] = (float)bkA;
            out[OFF_IDX + (size_t)bB * NSUB + n] = (float)bkB;
        }
    }

    // Finish any残 zero-fill rows (zrow covers 512 within the loops: 96 bursts
    // x 6 = 576 >= 512, so this is a no-op safety net)
    for (; zrow < 512; zrow++) {
        float* dst = out + OFF_ONEHOT + ((size_t)((rowbase + zrow) * NSUB + n)) * KC + tid;
        dst[0] = 0.0f; dst[256] = 0.0f; dst[512] = 0.0f; dst[768] = 0.0f;
    }

    // All zero-fills precede this barrier; the single ones after.
    __syncthreads();
    out[OFF_ONEHOT + ((size_t)bA * NSUB + n) * KC + bkA_last] = 1.0f;
    out[OFF_ONEHOT + ((size_t)bB * NSUB + n) * KC + bkB_last] = 1.0f;
}

// ---------------- kernel 3: z_q gather + z_q_out + loss ----------------
__global__ void gather_out_kernel(const float* __restrict__ z,
                                  const float* __restrict__ bias,
                                  float* __restrict__ out) {
    const int b = blockIdx.x;
    const int j = threadIdx.x;
    __shared__ int sidx[48];
    __shared__ float sred[8];

    if (j < 48) sidx[j] = g_idx[(size_t)b * 48 + j];
    __syncthreads();

    float acc = 0.0f;
#pragma unroll
    for (int n = 0; n < NSUB; n++) {
#pragma unroll
        for (int d = 0; d < DEPTHQ; d++) {
            const int k = sidx[n * 3 + d];
            acc += g_P[(((size_t)n << 10) + k) * DIMQ + j];
        }
    }
    const float zq = acc * (1.0f / 3.0f) + bias[j];
    const float zv = z[(size_t)b * DIMQ + j];
    const float diff = zq - zv;
    out[OFF_ZQ + (size_t)b * DIMQ + j] = zv + diff;

    float p = diff * diff;
#pragma unroll
    for (int off = 16; off > 0; off >>= 1) p += __shfl_down_sync(0xffffffffu, p, off);
    if ((j & 31) == 0) sred[j >> 5] = p;
    __syncthreads();
    if (j == 0) {
        float s = 0.0f;
#pragma unroll
        for (int i = 0; i < 8; i++) s += sred[i];
        atomicAdd(out + OFF_LOSS, s * (1.25f / (float)(BQ * DIMQ)));
    }
}

// ---------------- launcher ----------------
extern "C" void kernel_launch(void* const* d_in, const int* in_sizes, int n_in,
                              void* d_out, int out_size) {
    const float* z    = (const float*)d_in[0];
    const float* emb  = (const float*)d_in[1];
    const float* W    = (const float*)d_in[2];
    const float* bias = (const float*)d_in[3];
    float* out = (float*)d_out;

    (void)in_sizes; (void)n_in; (void)out_size;

    // vq first (independent of P) so ncu's sampled launch lands on vq.
    cudaFuncSetAttribute(vq_kernel, cudaFuncAttributeMaxDynamicSharedMemorySize, (int)VQ_SMEM);
    vq_kernel<<<dim3(16, 16), 256, VQ_SMEM>>>(z, emb, out);

    compute_P_kernel<<<1024, 256>>>(emb, W, out);

    gather_out_kernel<<<BQ, 256>>>(z, bias, out);
}